// round 17
// baseline (speedup 1.0000x reference)
#include <cuda_runtime.h>
#include <cuda_bf16.h>
#include <cstdint>

// Problem constants (fixed by the reference generator)
#define NGR   64
#define NPG   96
#define NODES (NGR*NPG)       // 6144
#define HID   64
#define INF   32
#define EF    16
#define DEG   8
#define EDGES (NODES*DEG)     // 49152
#define EPG   (NPG*DEG)       // 768
#define ECAP  40              // per-node out-edge capacity (binomial max << 40)

// ---------------- scratch (static device globals) ---------------------------
__device__ float g_M1[INF*HID];
__device__ float g_M2[EF*HID];
__device__ float g_bn[HID];
__device__ float g_be[HID];
__device__ float g_WA[INF*HID];
__device__ float g_WB[INF*HID];
__device__ float g_WC[EF*HID];
__device__ float g_biasA[HID];
__device__ float g_biasB[HID];
__device__ float g_biasC[HID];
__device__ float g_vecA[NODES*HID];
__device__ float g_vecB[NODES*HID];              // [node][m]  (m contiguous)
__device__ float g_Ce[(size_t)EDGES*HID];
__device__ unsigned short g_Bhi[64*64];          // W2 bf16 hi, SW128 image
__device__ unsigned short g_Blo[64*64];          // W2 bf16 lo, SW128 image
__device__ int       g_ecnt[NODES];
__device__ long long g_elist[(size_t)NODES*ECAP];

// ---------------- warp-MMA helpers (base-target PTX, sm_80+) ----------------
__device__ __forceinline__ void ldsm_x4(uint32_t* r, uint32_t addr) {
    asm volatile("ldmatrix.sync.aligned.m8n8.x4.shared.b16 {%0,%1,%2,%3}, [%4];"
                 : "=r"(r[0]), "=r"(r[1]), "=r"(r[2]), "=r"(r[3]) : "r"(addr));
}
__device__ __forceinline__ void ldsm_x2t(uint32_t* r, uint32_t addr) {
    asm volatile("ldmatrix.sync.aligned.m8n8.x2.trans.shared.b16 {%0,%1}, [%2];"
                 : "=r"(r[0]), "=r"(r[1]) : "r"(addr));
}
__device__ __forceinline__ void mma16816(float* d, const uint32_t* a, const uint32_t* b) {
    asm volatile(
        "mma.sync.aligned.m16n8k16.row.col.f32.bf16.bf16.f32 "
        "{%0,%1,%2,%3}, {%4,%5,%6,%7}, {%8,%9}, {%0,%1,%2,%3};"
        : "+f"(d[0]), "+f"(d[1]), "+f"(d[2]), "+f"(d[3])
        : "r"(a[0]), "r"(a[1]), "r"(a[2]), "r"(a[3]), "r"(b[0]), "r"(b[1]));
}
__device__ __forceinline__ uint32_t pack_bf16x2(float lo_elem, float hi_elem) {
    uint32_t r;
    asm("cvt.rn.satfinite.bf16x2.f32 %0, %1, %2;" : "=r"(r) : "f"(hi_elem), "f"(lo_elem));
    return r;
}
__device__ __forceinline__ uint32_t sw128(uint32_t off) {
    return off ^ ((off >> 3) & 0x70u);
}

// ---------------- K1a (+ W2 split + edge-count zeroing) ----------------------
#define P1N (INF*HID + EF*HID + 2*HID)     // 3200
#define P1W (P1N + 64*64)                  // + W2 image
#define P1T (P1W + NODES)                  // + counter zeroing
__global__ void prep1_kernel(const float* __restrict__ W_atom, const float* __restrict__ b_atom,
                             const float* __restrict__ W_bond, const float* __restrict__ b_bond,
                             const float* __restrict__ W_node, const float* __restrict__ b_node,
                             const float* __restrict__ W_edge, const float* __restrict__ b_edge,
                             const float* __restrict__ W2)
{
    int i = blockIdx.x * blockDim.x + threadIdx.x;
    if (i < INF*HID) {
        int r = i >> 6, k = i & 63;
        float s = 0.f;
        #pragma unroll 8
        for (int j = 0; j < HID; j++) s = fmaf(W_atom[r*HID+j], W_node[j*HID+k], s);
        g_M1[i] = s;
    } else if (i < INF*HID + EF*HID) {
        int i2 = i - INF*HID;
        int r = i2 >> 6, k = i2 & 63;
        float s = 0.f;
        #pragma unroll 8
        for (int j = 0; j < HID; j++) s = fmaf(W_bond[r*HID+j], W_edge[j*HID+k], s);
        g_M2[i2] = s;
    } else if (i < INF*HID + EF*HID + HID) {
        int k = i - (INF*HID + EF*HID);
        float s = b_node[k];
        #pragma unroll 8
        for (int j = 0; j < HID; j++) s = fmaf(b_atom[j], W_node[j*HID+k], s);
        g_bn[k] = s;
    } else if (i < P1N) {
        int k = i - (INF*HID + EF*HID + HID);
        float s = b_edge[k];
        #pragma unroll 8
        for (int j = 0; j < HID; j++) s = fmaf(b_bond[j], W_edge[j*HID+k], s);
        g_be[k] = s;
    } else if (i < P1W) {
        int i2 = i - P1N;
        int m = i2 >> 6, k = i2 & 63;
        float v = W2[m*HID + k];
        uint32_t b  = __float_as_uint(v);
        uint32_t hb = (b + 0x7FFFu + ((b >> 16) & 1u)) & 0xFFFF0000u;
        float hf = __uint_as_float(hb);
        float l  = v - hf;
        uint32_t lb32 = __float_as_uint(l);
        uint32_t lb   = (lb32 + 0x7FFFu + ((lb32 >> 16) & 1u)) & 0xFFFF0000u;
        uint32_t off = (uint32_t)m*128u + (uint32_t)k*2u;
        uint32_t sw  = sw128(off);
        g_Bhi[sw >> 1] = (unsigned short)(hb >> 16);
        g_Blo[sw >> 1] = (unsigned short)(lb >> 16);
    } else if (i < P1T) {
        g_ecnt[i - P1W] = 0;
    }
}

// ---------------- K1b ---------------------------------------------------------
__global__ void prep2_kernel(const float* __restrict__ W1, const float* __restrict__ b1)
{
    int i = blockIdx.x * blockDim.x + threadIdx.x;
    if (i < INF*HID) {
        int r = i >> 6, k = i & 63;
        float s = 0.f;
        #pragma unroll 8
        for (int j = 0; j < HID; j++) s = fmaf(g_M1[r*HID+j], W1[j*HID + k], s);
        g_WA[i] = s;
    } else if (i < 2*INF*HID) {
        int i2 = i - INF*HID;
        int r = i2 >> 6, k = i2 & 63;
        float s = 0.f;
        #pragma unroll 8
        for (int j = 0; j < HID; j++) s = fmaf(g_M1[r*HID+j], W1[(64+j)*HID + k], s);
        g_WB[i2] = s;
    } else if (i < 2*INF*HID + EF*HID) {
        int i2 = i - 2*INF*HID;
        int r = i2 >> 6, k = i2 & 63;
        float s = 0.f;
        #pragma unroll 8
        for (int j = 0; j < HID; j++) s = fmaf(g_M2[r*HID+j], W1[(128+j)*HID + k], s);
        g_WC[i2] = s;
    } else if (i < 2*INF*HID + EF*HID + HID) {
        int k = i - (2*INF*HID + EF*HID);
        float sa = b1[k], sb = 0.f, sc = 0.f;
        #pragma unroll 4
        for (int j = 0; j < HID; j++) {
            sa = fmaf(g_bn[j], W1[j*HID + k], sa);
            sb = fmaf(g_bn[j], W1[(64+j)*HID + k], sb);
            sc = fmaf(g_be[j], W1[(128+j)*HID + k], sc);
        }
        g_biasA[k] = sa;
        g_biasB[k] = sb;
        g_biasC[k] = sc;
    }
}

// ---------------- K2a: build per-node out-edge lists -------------------------
__global__ void edge_list_kernel(const int* __restrict__ edge_index)
{
    int e = blockIdx.x * blockDim.x + threadIdx.x;
    if (e >= EDGES) return;
    int u = edge_index[e];
    int v = edge_index[EDGES + e];
    int g = u / NPG;
    int p = atomicAdd(&g_ecnt[u], 1);
    if (p < ECAP)
        g_elist[(size_t)u*ECAP + p] = ((long long)e << 32) | (unsigned)(v - g*NPG);
}

// ---------------- K2b: batched per-node + per-edge layer-1 partials ----------
#define NODE_BLOCKS2 (NODES/4)     // 1536
#define EDGE_BLOCKS2 (EDGES/16)    // 3072
__global__ void encode_kernel(const float* __restrict__ x, const float* __restrict__ ea)
{
    if (blockIdx.x < NODE_BLOCKS2) {
        __shared__ float xr[4][INF];
        const int t  = threadIdx.x;
        const int ns = t >> 6;
        const int k  = t & 63;
        const int node = blockIdx.x*4 + ns;
        if (t < 4*INF) ((float*)xr)[t] = x[blockIdx.x*4*INF + t];
        __syncthreads();
        float sa = g_biasA[k], sb = g_biasB[k];
        #pragma unroll
        for (int f = 0; f < INF; f++) {
            float xv = xr[ns][f];
            sa = fmaf(xv, g_WA[f*HID + k], sa);
            sb = fmaf(xv, g_WB[f*HID + k], sb);
        }
        g_vecA[node*HID + k] = sa;
        g_vecB[node*HID + k] = sb;
    } else {
        __shared__ float er[16][EF];
        const int t   = threadIdx.x;
        const int grp = t >> 6;
        const int k   = t & 63;
        const int b   = blockIdx.x - NODE_BLOCKS2;
        const int e0  = b*16;
        ((float*)er)[t] = ea[(size_t)e0*EF + t];
        __syncthreads();
        const float bc = g_biasC[k];
        float s0 = bc, s1 = bc, s2 = bc, s3 = bc;
        #pragma unroll
        for (int f = 0; f < EF; f++) {
            float wc = g_WC[f*HID + k];
            s0 = fmaf(er[grp*4+0][f], wc, s0);
            s1 = fmaf(er[grp*4+1][f], wc, s1);
            s2 = fmaf(er[grp*4+2][f], wc, s2);
            s3 = fmaf(er[grp*4+3][f], wc, s3);
        }
        g_Ce[(size_t)(e0 + grp*4 + 0)*HID + k] = s0;
        g_Ce[(size_t)(e0 + grp*4 + 1)*HID + k] = s1;
        g_Ce[(size_t)(e0 + grp*4 + 2)*HID + k] = s2;
        g_Ce[(size_t)(e0 + grp*4 + 3)*HID + k] = s3;
    }
}

// ---------------- K3: warp-MMA pairwise MLP (1 node/block, 128 thr) ----------
#define SM_A_HI   0          // 96 x 128B = 12288
#define SM_A_LO   12288
#define SM_B_HI   24576      // 8192
#define SM_B_LO   32768      // 8192
#define SM_AU     40960      // 256
#define SM_B2     41216      // 256
#define SM_W3     41472      // 256
#define SM_EL     41728      // ECAP*8 = 320 -> pad 384
#define SM_E0     42112      // 384
#define SM_E1     42496      // 384
#define SM_NM     42880      // 384
#define SM_ECNT   43264      // 16
#define SM_RED    43280      // 96*4*4 = 1536
#define SM_TOTAL  44816

__global__ void __launch_bounds__(128, 4)
pair_kernel(const float* __restrict__ b2, const float* __restrict__ W3,
            const float* __restrict__ b3,
            float* __restrict__ out)
{
    extern __shared__ char smc[];
    const uint32_t sbase = (uint32_t)__cvta_generic_to_shared(smc);
    float*     Au_s = (float*)(smc + SM_AU);
    float*     b2s  = (float*)(smc + SM_B2);
    float*     W3s  = (float*)(smc + SM_W3);
    long long* el   = (long long*)(smc + SM_EL);
    int*       e0s  = (int*)(smc + SM_E0);
    int*       e1s  = (int*)(smc + SM_E1);
    int*       nms  = (int*)(smc + SM_NM);
    int*       ecs  = (int*)(smc + SM_ECNT);
    float*     red  = (float*)(smc + SM_RED);   // [96][4]

    const int t   = threadIdx.x;          // 0..127
    const int wid = t >> 5;
    const int lid = t & 31;
    const int u   = blockIdx.x;
    const int g   = u / NPG;

    // one coalesced phase: B tiles + edge list + small vectors
    {
        const uint4* bh = (const uint4*)g_Bhi;
        const uint4* bl = (const uint4*)g_Blo;
        uint4* dh = (uint4*)(smc + SM_B_HI);
        uint4* dl = (uint4*)(smc + SM_B_LO);
        #pragma unroll
        for (int i = t; i < 512; i += 128) { dh[i] = bh[i]; dl[i] = bl[i]; }
    }
    if (t == 0) ecs[0] = min(g_ecnt[u], ECAP);
    if (t < ECAP) el[t] = g_elist[(size_t)u*ECAP + t];
    if (t < 64) {
        Au_s[t] = g_vecA[(size_t)u*HID + t];
        b2s[t]  = b2[t];
        W3s[t]  = W3[t];
    }
    __syncthreads();
    const int ec = ecs[0];
    if (t == 0) {                       // deterministic order (tiny list)
        for (int a = 1; a < ec; a++) {
            long long v = el[a]; int b = a - 1;
            while (b >= 0 && el[b] > v) { el[b+1] = el[b]; b--; }
            el[b+1] = v;
        }
    }
    __syncthreads();
    if (t < 96) {                       // per-row match table
        int e0 = -1, e1 = -1, nm = 0;
        for (int q = 0; q < ec; q++) {
            long long pk = el[q];
            if ((int)(pk & 0xffffffffLL) == t) {
                int e = (int)(pk >> 32);
                if (nm == 0) e0 = e; else if (nm == 1) e1 = e;
                nm++;
            }
        }
        e0s[t] = e0; e1s[t] = e1; nms[t] = nm;
    }
    __syncthreads();

    // ---- build A tile with prefetch double-buffer ----
    {
        const int rip = t >> 4;                 // row-in-pass 0..7
        const int l   = t & 15;                 // lane's 4 m-values
        const float4* au4 = (const float4*)Au_s;
        const float4 a = au4[l];
        float4 vnext = *(const float4*)(g_vecB + (size_t)(g*NPG + rip)*HID + l*4);
        for (int pass = 0; pass < 12; pass++) {
            const int j = pass*8 + rip;
            float4 v = vnext;
            if (pass < 11)
                vnext = *(const float4*)(g_vecB + (size_t)(g*NPG + j + 8)*HID + l*4);
            v.x += a.x; v.y += a.y; v.z += a.z; v.w += a.w;
            const int nm = nms[j];
            if (nm > 0) {
                float4 c = ((const float4*)(g_Ce + (size_t)e0s[j]*HID))[l];
                v.x += c.x; v.y += c.y; v.z += c.z; v.w += c.w;
                if (nm >= 2) {
                    c = ((const float4*)(g_Ce + (size_t)e1s[j]*HID))[l];
                    v.x += c.x; v.y += c.y; v.z += c.z; v.w += c.w;
                }
                if (nm > 2) {
                    int seen = 0;
                    for (int q = 0; q < ec; q++) {
                        long long pk = el[q];
                        if ((int)(pk & 0xffffffffLL) == j) {
                            seen++;
                            if (seen > 2) {
                                int e = (int)(pk >> 32);
                                c = ((const float4*)(g_Ce + (size_t)e*HID))[l];
                                v.x += c.x; v.y += c.y; v.z += c.z; v.w += c.w;
                            }
                        }
                    }
                }
            }
            v.x = fmaxf(v.x, 0.f); v.y = fmaxf(v.y, 0.f);
            v.z = fmaxf(v.z, 0.f); v.w = fmaxf(v.w, 0.f);
            uint32_t hi01 = pack_bf16x2(v.x, v.y);
            uint32_t hi23 = pack_bf16x2(v.z, v.w);
            float hx = __uint_as_float(hi01 << 16);
            float hy = __uint_as_float(hi01 & 0xFFFF0000u);
            float hz = __uint_as_float(hi23 << 16);
            float hw = __uint_as_float(hi23 & 0xFFFF0000u);
            uint32_t lo01 = pack_bf16x2(v.x - hx, v.y - hy);
            uint32_t lo23 = pack_bf16x2(v.z - hz, v.w - hw);
            uint32_t sw = sw128((uint32_t)j*128u + (uint32_t)l*8u);
            *(uint2*)(smc + SM_A_HI + sw) = make_uint2(hi01, hi23);
            *(uint2*)(smc + SM_A_LO + sw) = make_uint2(lo01, lo23);
        }
    }
    __syncthreads();

    // ---- warp-MMA GEMM: C[96,64] = A @ B; warp owns n-tiles {2w, 2w+1} ----
    uint32_t Bh[2][4][2], Bl[2][4][2];
    #pragma unroll
    for (int nt2 = 0; nt2 < 2; nt2++) {
        const int nt = 2*wid + nt2;
        #pragma unroll
        for (int ks = 0; ks < 4; ks++) {
            uint32_t off = (uint32_t)(ks*16 + (lid & 15))*128u + (uint32_t)nt*16u;
            uint32_t sw  = sw128(off);
            ldsm_x2t(Bh[nt2][ks], sbase + SM_B_HI + sw);
            ldsm_x2t(Bl[nt2][ks], sbase + SM_B_LO + sw);
        }
    }

    float acc[6][2][4];
    #pragma unroll
    for (int mt = 0; mt < 6; mt++)
        #pragma unroll
        for (int n2 = 0; n2 < 2; n2++)
            #pragma unroll
            for (int q = 0; q < 4; q++) acc[mt][n2][q] = 0.f;

    #pragma unroll
    for (int mt = 0; mt < 6; mt++) {
        #pragma unroll
        for (int ks = 0; ks < 4; ks++) {
            uint32_t off = (uint32_t)(mt*16 + (lid & 15))*128u
                         + (uint32_t)ks*32u + (uint32_t)(lid >> 4)*16u;
            uint32_t sw  = sw128(off);
            uint32_t Ah[4], Al[4];
            ldsm_x4(Ah, sbase + SM_A_HI + sw);
            ldsm_x4(Al, sbase + SM_A_LO + sw);
            #pragma unroll
            for (int nt2 = 0; nt2 < 2; nt2++) {
                mma16816(acc[mt][nt2], Ah, Bh[nt2][ks]);
                mma16816(acc[mt][nt2], Ah, Bl[nt2][ks]);
                mma16816(acc[mt][nt2], Al, Bh[nt2][ks]);
            }
        }
    }

    // ---- epilogue: relu(h1+b2)*W3 on fragments, quad-shfl, cross-warp smem --
    {
        const int g4 = lid >> 2;
        const int tg = lid & 3;
        #pragma unroll
        for (int mt = 0; mt < 6; mt++) {
            float pg = 0.f, pg8 = 0.f;
            #pragma unroll
            for (int nt2 = 0; nt2 < 2; nt2++) {
                const int c0 = (2*wid + nt2)*8 + tg*2;
                const float* d = acc[mt][nt2];
                float w0 = W3s[c0], w1 = W3s[c0+1];
                float bb0 = b2s[c0], bb1 = b2s[c0+1];
                pg  = fmaf(fmaxf(d[0] + bb0, 0.f), w0, pg);
                pg  = fmaf(fmaxf(d[1] + bb1, 0.f), w1, pg);
                pg8 = fmaf(fmaxf(d[2] + bb0, 0.f), w0, pg8);
                pg8 = fmaf(fmaxf(d[3] + bb1, 0.f), w1, pg8);
            }
            pg  += __shfl_xor_sync(0xffffffffu, pg, 1, 4);
            pg  += __shfl_xor_sync(0xffffffffu, pg, 2, 4);
            pg8 += __shfl_xor_sync(0xffffffffu, pg8, 1, 4);
            pg8 += __shfl_xor_sync(0xffffffffu, pg8, 2, 4);
            if (tg == 0) {
                red[(mt*16 + g4)*4 + wid]     = pg;
                red[(mt*16 + g4 + 8)*4 + wid] = pg8;
            }
        }
    }
    __syncthreads();
    if (t < 96) {
        float sv = (red[t*4+0] + red[t*4+1]) + (red[t*4+2] + red[t*4+3]);
        out[(size_t)u*NPG + t] = sv + b3[0];
    }
}

// ---------------- launch -----------------------------------------------------
extern "C" void kernel_launch(void* const* d_in, const int* in_sizes, int n_in,
                              void* d_out, int out_size)
{
    const float* x          = (const float*)d_in[0];
    const float* edge_attr  = (const float*)d_in[1];
    const int*   edge_index = (const int*)  d_in[2];

    int w = 6;
    if (n_in >= 6 && in_sizes[5] != 1) w = 5;
    if (n_in == 19) w = 5;
    const float* W_atom = (const float*)d_in[w+0];
    const float* b_atom = (const float*)d_in[w+1];
    const float* W_bond = (const float*)d_in[w+2];
    const float* b_bond = (const float*)d_in[w+3];
    const float* W_node = (const float*)d_in[w+4];
    const float* b_node = (const float*)d_in[w+5];
    const float* W_edge = (const float*)d_in[w+6];
    const float* b_edge = (const float*)d_in[w+7];
    const float* W1     = (const float*)d_in[w+8];
    const float* b1     = (const float*)d_in[w+9];
    const float* W2     = (const float*)d_in[w+10];
    const float* b2     = (const float*)d_in[w+11];
    const float* W3     = (const float*)d_in[w+12];
    const float* b3     = (const float*)d_in[w+13];

    cudaFuncSetAttribute(pair_kernel, cudaFuncAttributeMaxDynamicSharedMemorySize, SM_TOTAL);

    const int P2 = 2*INF*HID + EF*HID + HID;             // 5184
    prep1_kernel<<<(P1T + 255)/256, 256>>>(W_atom, b_atom, W_bond, b_bond,
                                           W_node, b_node, W_edge, b_edge, W2);
    prep2_kernel<<<(P2 + 255)/256, 256>>>(W1, b1);
    edge_list_kernel<<<EDGES/256, 256>>>(edge_index);
    encode_kernel<<<NODE_BLOCKS2 + EDGE_BLOCKS2, 256>>>(x, edge_attr);
    pair_kernel<<<NODES, 128, SM_TOTAL>>>(b2, W3, b3, (float*)d_out);
}